// round 16
// baseline (speedup 1.0000x reference)
#include <cuda_runtime.h>
#include <cuda_bf16.h>
#include <cstdint>

#define NN 16384
#define DD 256
#define BM 128
#define NTILES (NN / 128)             // 128
#define NHALF (NTILES * 2)            // 256 half-tiles of 128x64
#define TILE_BYTES (BM * DD * 2)      // 65536 (bf16)
#define THREADS 384                   // 12 warps: 3 tile-groups of 4

// A: per 128-row tile, row-major 512B rows with 16B-chunk XOR swizzle (ldmatrix).
// B: per 128-col tile, MMA-fragment order: 128 blocks of 512B, block = (nf2*16+ks).
__device__ __align__(128) __nv_bfloat16 g_flB[NN * DD];  // 8 MB, pre-scaled by 1/(T*ln2)
__device__ __align__(128) __nv_bfloat16 g_fgB[NN * DD];  // 8 MB
__device__ float g_diag[NN];                             // exact diagonal (log2 units)
__device__ float g_bsum[NN / BM];

// ---------------------------------------------------------------------------
__device__ __forceinline__ uint32_t smem_u32(const void* p) {
    uint32_t a;
    asm("{ .reg .u64 t; cvta.to.shared.u64 t, %1; cvt.u32.u64 %0, t; }" : "=r"(a) : "l"(p));
    return a;
}
__device__ __forceinline__ float ex2f(float x) {
    float y; asm("ex2.approx.ftz.f32 %0, %1;" : "=f"(y) : "f"(x)); return y;
}
__device__ __forceinline__ float lg2f(float x) {
    float y; asm("lg2.approx.ftz.f32 %0, %1;" : "=f"(y) : "f"(x)); return y;
}

#define MBARRIER_INIT(mbar, count) \
    asm volatile("mbarrier.init.shared.b64 [%0], %1;" :: "r"((uint32_t)(mbar)), "r"((uint32_t)(count)) : "memory")
#define MBARRIER_EXPECT_TX(mbar, bytes) \
    asm volatile("mbarrier.arrive.expect_tx.shared.b64 _, [%0], %1;" :: "r"((uint32_t)(mbar)), "r"((uint32_t)(bytes)) : "memory")
#define MBARRIER_WAIT_PARITY(mbar, parity) do { \
    uint32_t _m = (uint32_t)(mbar); uint32_t _p = (uint32_t)(parity); uint32_t _d; \
    asm volatile("{\n\t.reg .pred p;\n\t" \
        "mbarrier.try_wait.parity.acquire.cta.shared::cta.b64 p, [%1], %2;\n\t" \
        "selp.b32 %0, 1, 0, p;\n\t}" : "=r"(_d) : "r"(_m), "r"(_p) : "memory"); \
    if (!_d) { \
        asm volatile("{\n\t.reg .pred P1;\n\t" \
            "WL_%=:\n\t" \
            "mbarrier.try_wait.parity.acquire.cta.shared::cta.b64 P1, [%0], %1, 0x989680;\n\t" \
            "@P1 bra.uni WD_%=;\n\t" \
            "bra.uni WL_%=;\n\t" \
            "WD_%=:\n\t}" :: "r"(_m), "r"(_p) : "memory"); \
    } \
} while (0)

__device__ __forceinline__ void bulk_copy(uint32_t dst_smem, const void* src, uint32_t bytes,
                                          uint32_t mbar) {
    asm volatile("cp.async.bulk.shared::cta.global.mbarrier::complete_tx::bytes [%0], [%1], %2, [%3];"
                 :: "r"(dst_smem), "l"(src), "r"(bytes), "r"(mbar) : "memory");
}
__device__ __forceinline__ void ldsm4(uint32_t* r, uint32_t addr) {
    asm volatile("ldmatrix.sync.aligned.m8n8.x4.shared.b16 {%0,%1,%2,%3}, [%4];"
                 : "=r"(r[0]), "=r"(r[1]), "=r"(r[2]), "=r"(r[3]) : "r"(addr));
}
__device__ __forceinline__ void mma16816(float* d, const uint32_t* a, uint32_t b0, uint32_t b1) {
    asm volatile("mma.sync.aligned.m16n8k16.row.col.f32.bf16.bf16.f32 "
                 "{%0,%1,%2,%3}, {%4,%5,%6,%7}, {%8,%9}, {%0,%1,%2,%3};"
                 : "+f"(d[0]), "+f"(d[1]), "+f"(d[2]), "+f"(d[3])
                 : "r"(a[0]), "r"(a[1]), "r"(a[2]), "r"(a[3]), "r"(b0), "r"(b1));
}

// ---------------------------------------------------------------------------
// Kernel A: L2-normalize, scale (A side by 1/(T*ln2)), bf16-pack.
// which=0: A swizzled-row layout. which=1: B fragment layout.
// ---------------------------------------------------------------------------
__global__ void __launch_bounds__(256) norm_pack_kernel(const float* __restrict__ in, int which) {
    char* outB = (char*)(which ? g_fgB : g_flB);
    const float extra = which ? 1.0f : (float)(1.0 / (0.07 * 0.6931471805599453));
    const int wid = threadIdx.x >> 5;
    const int lane = threadIdx.x & 31;
    const int row = blockIdx.x * 8 + wid;

    const float4* r4 = (const float4*)(in + (size_t)row * DD);
    float4 a = r4[2 * lane];
    float4 b = r4[2 * lane + 1];

    float ss = a.x * a.x + a.y * a.y + a.z * a.z + a.w * a.w
             + b.x * b.x + b.y * b.y + b.z * b.z + b.w * b.w;
    #pragma unroll
    for (int off = 16; off > 0; off >>= 1)
        ss += __shfl_xor_sync(0xffffffffu, ss, off);
    float s = extra / fmaxf(sqrtf(ss), 1e-12f);

    __nv_bfloat162 h0 = __floats2bfloat162_rn(a.x * s, a.y * s);
    __nv_bfloat162 h1 = __floats2bfloat162_rn(a.z * s, a.w * s);
    __nv_bfloat162 h2 = __floats2bfloat162_rn(b.x * s, b.y * s);
    __nv_bfloat162 h3 = __floats2bfloat162_rn(b.z * s, b.w * s);
    uint32_t hv[4] = {*(uint32_t*)&h0, *(uint32_t*)&h1, *(uint32_t*)&h2, *(uint32_t*)&h3};

    const int t = row >> 7;            // tile
    char* tbase = outB + (size_t)t * TILE_BYTES;

    if (!which) {
        const int r = row & 127;
        const uint32_t off = (uint32_t)r * 512u + (uint32_t)((lane ^ (r & 7)) << 4);
        uint4 packed; packed.x = hv[0]; packed.y = hv[1]; packed.z = hv[2]; packed.w = hv[3];
        *(uint4*)(tbase + off) = packed;
    } else {
        // B fragment layout. This row is column n; lane holds k pairs p=4*lane+j.
        const int nl = row & 127;
        const int nf2 = nl >> 4;
        const int gl = nl & 15;
        const int g = gl & 7;
        const int ghi = gl >> 3;
        const int ks = lane >> 1;
        const int hi = lane & 1;
        char* blk = tbase + (uint32_t)(nf2 * 16 + ks) * 512u;
        #pragma unroll
        for (int j = 0; j < 4; j++)
            *(uint32_t*)(blk + (uint32_t)((g * 4 + j) * 16 + (ghi * 2 + hi) * 4)) = hv[j];
    }
}

// ---------------------------------------------------------------------------
// Kernel D (launch 3): exact fp32 diagonal: diag[r] = dot(fl_n[r], fg_n[r]) * K2.
// One warp per row.
// ---------------------------------------------------------------------------
__global__ void __launch_bounds__(256) diag_kernel(const float* __restrict__ in_l,
                                                   const float* __restrict__ in_g) {
    const int wid = threadIdx.x >> 5;
    const int lane = threadIdx.x & 31;
    const int row = blockIdx.x * 8 + wid;

    const float4* l4 = (const float4*)(in_l + (size_t)row * DD);
    const float4* g4 = (const float4*)(in_g + (size_t)row * DD);
    float sl = 0.0f, sg = 0.0f, dt = 0.0f;
    #pragma unroll
    for (int j = 0; j < 2; j++) {
        float4 a = l4[2 * lane + j];
        float4 b = g4[2 * lane + j];
        sl += a.x * a.x + a.y * a.y + a.z * a.z + a.w * a.w;
        sg += b.x * b.x + b.y * b.y + b.z * b.z + b.w * b.w;
        dt += a.x * b.x + a.y * b.y + a.z * b.z + a.w * b.w;
    }
    #pragma unroll
    for (int off = 16; off > 0; off >>= 1) {
        sl += __shfl_xor_sync(0xffffffffu, sl, off);
        sg += __shfl_xor_sync(0xffffffffu, sg, off);
        dt += __shfl_xor_sync(0xffffffffu, dt, off);
    }
    if (lane == 0) {
        const float K2 = (float)(1.0 / (0.07 * 0.6931471805599453));
        g_diag[row] = dt * K2 / (fmaxf(sqrtf(sl), 1e-12f) * fmaxf(sqrtf(sg), 1e-12f));
    }
}

// ---------------------------------------------------------------------------
// Kernel B: HMMA GEMM + fused LSE. 12 warps in 3 tile-groups of 4; group g
// sweeps half-tiles ht = 3j+g (barrier-free). Warp tile 64x32 (acc 64 regs).
// Both A fragments (ldsm) and B fragments (LDG) double-buffered at distance 1.
// ---------------------------------------------------------------------------
__global__ void __launch_bounds__(THREADS, 1) gemm_lse_kernel() {
    extern __shared__ __align__(128) char smem_raw[];
    const uint32_t sbase0 = smem_u32(smem_raw);
    const uint32_t cb = (sbase0 + 1023) & ~1023u;
    char* cptr = smem_raw + (cb - sbase0);

    const uint32_t MB_A = cb + 0;
    float* red_s   = (float*)(cptr + 64);    // [128][6]
    float* sloss_s = (float*)(cptr + 3136);  // [128]
    const uint32_t A_S = cb + 8192;

    const int tid = threadIdx.x;
    const int lane = tid & 31;
    const int w = tid >> 5;
    const int g = w >> 2;                    // tile-group 0..2
    const int wl = w & 3;
    const int wm = wl >> 1;                  // M half (64 rows)
    const int wn = wl & 1;                   // 32-col half of the 64-col half-tile
    const int bx = blockIdx.x;

    if (tid == 0) MBARRIER_INIT(MB_A, 1);
    __syncthreads();
    if (tid == 0) {
        MBARRIER_EXPECT_TX(MB_A, TILE_BYTES);
        bulk_copy(A_S, (const char*)g_flB + (size_t)bx * TILE_BYTES, TILE_BYTES, MB_A);
    }

    // A ldmatrix addressing (swizzled 512B rows)
    const uint32_t xl = (uint32_t)(lane & 7);
    const int kbA = (lane >> 4) & 1;
    const int rbA = (lane >> 3) & 1;
    uint32_t aBase[4];
    #pragma unroll
    for (int mf = 0; mf < 4; mf++)
        aBase[mf] = A_S + (uint32_t)(wm * 64 + mf * 16 + (lane & 7) + rbA * 8) * 512u;

    const char* __restrict__ bAll = (const char*)g_fgB;
    const uint32_t bLane = (uint32_t)lane * 16u;

    float rs[8];
    #pragma unroll
    for (int j = 0; j < 8; j++) rs[j] = 0.0f;

    MBARRIER_WAIT_PARITY(MB_A, 0);

    for (int ht = g; ht < NHALF; ht += 3) {
        const int i = ht >> 1;               // tile index
        const int nh = ht & 1;               // 64-col half
        const int nf2base = nh * 4 + wn * 2;
        const char* __restrict__ bW = bAll + (size_t)i * TILE_BYTES
                                    + (uint32_t)(nf2base * 16) * 512u + bLane;

        float acc[4][4][4];                  // [mf][q*2+s8][h*2+cc]
        #pragma unroll
        for (int mf = 0; mf < 4; mf++)
            #pragma unroll
            for (int nf = 0; nf < 4; nf++)
                #pragma unroll
                for (int c = 0; c < 4; c++) acc[mf][nf][c] = 0.0f;

        uint32_t afA[4][4], afB[4][4];
        uint4 bf0[2], bf1[2];
        {
            const uint32_t c0 = (uint32_t)((0 + kbA) ^ (int)xl) << 4;
            #pragma unroll
            for (int mf = 0; mf < 4; mf++) ldsm4(afA[mf], aBase[mf] + c0);
            #pragma unroll
            for (int q = 0; q < 2; q++)
                bf0[q] = *(const uint4*)(bW + (uint32_t)(q * 16) * 512u);
        }

        #pragma unroll
        for (int ks = 0; ks < 16; ks++) {
            uint32_t (*cur)[4] = (ks & 1) ? afB : afA;
            uint32_t (*nxt)[4] = (ks & 1) ? afA : afB;
            uint4* bcur = (ks & 1) ? bf1 : bf0;
            uint4* bnxt = (ks & 1) ? bf0 : bf1;
            if (ks + 1 < 16) {
                const uint32_t cN = (uint32_t)((2 * (ks + 1) + kbA) ^ (int)xl) << 4;
                #pragma unroll
                for (int mf = 0; mf < 4; mf++) ldsm4(nxt[mf], aBase[mf] + cN);
                #pragma unroll
                for (int q = 0; q < 2; q++)
                    bnxt[q] = *(const uint4*)(bW + (uint32_t)(q * 16 + ks + 1) * 512u);
            }
            #pragma unroll
            for (int mf = 0; mf < 4; mf++)
                #pragma unroll
                for (int q = 0; q < 2; q++) {
                    mma16816(acc[mf][q * 2],     cur[mf], bcur[q].x, bcur[q].y);
                    mma16816(acc[mf][q * 2 + 1], cur[mf], bcur[q].z, bcur[q].w);
                }
        }

        #pragma unroll
        for (int mf = 0; mf < 4; mf++)
            #pragma unroll
            for (int nf = 0; nf < 4; nf++) {
                rs[mf * 2 + 0] += ex2f(acc[mf][nf][0]) + ex2f(acc[mf][nf][1]);
                rs[mf * 2 + 1] += ex2f(acc[mf][nf][2]) + ex2f(acc[mf][nf][3]);
            }
    }

    // lanes l, l^1, l^2 share the same rows
    #pragma unroll
    for (int j = 0; j < 8; j++) {
        rs[j] += __shfl_xor_sync(0xffffffffu, rs[j], 1);
        rs[j] += __shfl_xor_sync(0xffffffffu, rs[j], 2);
    }
    if ((lane & 3) == 0) {
        const int gq = lane >> 2;
        #pragma unroll
        for (int mf = 0; mf < 4; mf++)
            #pragma unroll
            for (int h = 0; h < 2; h++) {
                int R = wm * 64 + mf * 16 + gq + h * 8;
                red_s[R * 6 + g * 2 + wn] = rs[mf * 2 + h];
            }
    }
    __syncthreads();

    if (tid < 128) {
        float tot = 0.0f;
        #pragma unroll
        for (int c = 0; c < 6; c++) tot += red_s[tid * 6 + c];
        sloss_s[tid] = 0.6931471805599453f * (lg2f(tot) - g_diag[bx * 128 + tid]);
    }
    __syncthreads();
    if (tid == 0) {
        float t = 0.0f;
        #pragma unroll 8
        for (int r = 0; r < BM; r++) t += sloss_s[r];
        g_bsum[bx] = t;
    }
}

// ---------------------------------------------------------------------------
__global__ void finalize_kernel(float* __restrict__ out) {
    __shared__ float sh[128];
    const int t = threadIdx.x;
    sh[t] = g_bsum[t];
    __syncthreads();
    #pragma unroll
    for (int off = 64; off > 0; off >>= 1) {
        if (t < off) sh[t] += sh[t + off];
        __syncthreads();
    }
    if (t == 0) out[0] = sh[0] / (float)NN;
}

// ---------------------------------------------------------------------------
extern "C" void kernel_launch(void* const* d_in, const int* in_sizes, int n_in,
                              void* d_out, int out_size) {
    const float* feat_local  = (const float*)d_in[0];
    const float* feat_global = (const float*)d_in[1];
    float* out = (float*)d_out;

    const int smem_bytes = 1024 + 8192 + TILE_BYTES;  // ~73 KB (A only)
    static bool attr_set = false;
    if (!attr_set) {
        cudaFuncSetAttribute(gemm_lse_kernel,
                             cudaFuncAttributeMaxDynamicSharedMemorySize, smem_bytes);
        attr_set = true;
    }

    norm_pack_kernel<<<NN / 8, 256>>>(feat_local, 0);        // launch 1
    norm_pack_kernel<<<NN / 8, 256>>>(feat_global, 1);       // launch 2
    diag_kernel<<<NN / 8, 256>>>(feat_local, feat_global);   // launch 3
    gemm_lse_kernel<<<NN / BM, THREADS, smem_bytes>>>();     // launch 4  <- profiled
    finalize_kernel<<<1, 128>>>(out);                        // launch 5
}